// round 14
// baseline (speedup 1.0000x reference)
#include <cuda_runtime.h>
#include <cstdint>

// ---------------- problem constants (fixed by reference setup) ----------------
#define N_SRC0 100000
#define N_DST0 20000
#define N_DST1 4000
#define NEDGE0 500000
#define NEDGE1 100000
#define D_IN 128
#define D_H 256

#define CSR_BLOCKS 296   // 2 per SM -> co-residency guaranteed (8 warps/block)

// ---------------- scratch (device globals; no allocation allowed) -------------
__device__ float g_mean0[N_DST0 * D_IN];
__device__ float g_h[N_DST0 * D_H];
__device__ float g_mean1[N_DST1 * D_H];
__device__ float g_out[N_DST1 * D_H];

__device__ int g_cnt0[N_DST0];      // zero at load; re-zeroed by scan phase
__device__ int g_rowptr0[N_DST0 + 1];
__device__ int g_cursor0[N_DST0];
__device__ int g_col0[NEDGE0];
__device__ int g_cnt1[N_DST1];
__device__ int g_rowptr1[N_DST1 + 1];
__device__ int g_cursor1[N_DST1];
__device__ int g_col1[NEDGE1];

// grid barrier state (generation monotonic across replays -> deterministic)
__device__ unsigned g_bar_arrive;
__device__ volatile unsigned g_bar_gen;

__device__ __forceinline__ void grid_sync(unsigned nb) {
    __syncthreads();
    if (threadIdx.x == 0) {
        unsigned gen = g_bar_gen;
        __threadfence();
        if (atomicAdd(&g_bar_arrive, 1u) == nb - 1) {
            g_bar_arrive = 0;
            __threadfence();
            g_bar_gen = gen + 1;
        } else {
            while (g_bar_gen == gen) { }
        }
        __threadfence();
    }
    __syncthreads();
}

// ---------------- fused CSR build: count -> scan -> fill (one kernel) ---------
__device__ __forceinline__ void scan_phase(int* cnt, int* rowptr, int* cursor,
                                           int n, int* wsum, int* carry_s) {
    const int tid  = threadIdx.x;
    const int lane = tid & 31;
    const int wid  = tid >> 5;
    if (tid == 0) *carry_s = 0;
    __syncthreads();
    const int4 z4 = make_int4(0, 0, 0, 0);
    for (int base = 0; base < n; base += 2048) {      // 256 thr * 8
        int i0 = base + tid * 8;
        int v[8];
        if (i0 + 8 <= n) {
            int4 a = *(const int4*)&cnt[i0];
            int4 b = *(const int4*)&cnt[i0 + 4];
            v[0] = a.x; v[1] = a.y; v[2] = a.z; v[3] = a.w;
            v[4] = b.x; v[5] = b.y; v[6] = b.z; v[7] = b.w;
            *(int4*)&cnt[i0] = z4;                    // restore zero
            *(int4*)&cnt[i0 + 4] = z4;
        } else {
#pragma unroll
            for (int j = 0; j < 8; j++) {
                int ok = (i0 + j < n);
                v[j] = ok ? cnt[i0 + j] : 0;
                if (ok) cnt[i0 + j] = 0;
            }
        }
        int incl[8];
        int s = 0;
#pragma unroll
        for (int j = 0; j < 8; j++) { s += v[j]; incl[j] = s; }
        const int tot = s;
        int ws = tot;
#pragma unroll
        for (int off = 1; off < 32; off <<= 1) {
            int t = __shfl_up_sync(0xffffffffu, ws, off);
            if (lane >= off) ws += t;
        }
        if (lane == 31) wsum[wid] = ws;
        __syncthreads();
        if (wid == 0 && lane < 8) {
            int w2 = wsum[lane];
#pragma unroll
            for (int off = 1; off < 8; off <<= 1) {
                int t = __shfl_up_sync(0xffu, w2, off);
                if (lane >= off) w2 += t;
            }
            wsum[lane] = w2;
        }
        __syncthreads();
        int off0 = *carry_s + ((wid > 0) ? wsum[wid - 1] : 0) + (ws - tot);
        if (i0 + 8 <= n) {
            int4 r0, r1;
            r0.x = off0 + incl[0] - v[0]; r0.y = off0 + incl[1] - v[1];
            r0.z = off0 + incl[2] - v[2]; r0.w = off0 + incl[3] - v[3];
            r1.x = off0 + incl[4] - v[4]; r1.y = off0 + incl[5] - v[5];
            r1.z = off0 + incl[6] - v[6]; r1.w = off0 + incl[7] - v[7];
            *(int4*)&rowptr[i0] = r0; *(int4*)&rowptr[i0 + 4] = r1;
            *(int4*)&cursor[i0] = r0; *(int4*)&cursor[i0 + 4] = r1;
        } else {
#pragma unroll
            for (int j = 0; j < 8; j++)
                if (i0 + j < n) {
                    int e = off0 + incl[j] - v[j];
                    rowptr[i0 + j] = e; cursor[i0 + j] = e;
                }
        }
        __syncthreads();
        if (tid == 0) *carry_s += wsum[7];
        __syncthreads();
    }
    if (tid == 0) rowptr[n] = *carry_s;
}

__global__ void __launch_bounds__(256, 2)
csr_build_kernel(const int* __restrict__ ei0, const int* __restrict__ ei1) {
    __shared__ int wsum[8];
    __shared__ int carry_s;
    const int Q0 = NEDGE0 / 8, Q1 = NEDGE1 / 8;
    const int QT = Q0 + Q1;
    const int gthreads = CSR_BLOCKS * 256;
    int t0 = blockIdx.x * 256 + threadIdx.x;

    // ---- phase 1: count ----
    for (int t = t0; t < QT; t += gthreads) {
        if (t < Q0) {
            int4 a = ((const int4*)(ei0 + NEDGE0))[t * 2];
            int4 b = ((const int4*)(ei0 + NEDGE0))[t * 2 + 1];
            atomicAdd(&g_cnt0[a.x], 1); atomicAdd(&g_cnt0[a.y], 1);
            atomicAdd(&g_cnt0[a.z], 1); atomicAdd(&g_cnt0[a.w], 1);
            atomicAdd(&g_cnt0[b.x], 1); atomicAdd(&g_cnt0[b.y], 1);
            atomicAdd(&g_cnt0[b.z], 1); atomicAdd(&g_cnt0[b.w], 1);
        } else {
            int u = t - Q0;
            int4 a = ((const int4*)(ei1 + NEDGE1))[u * 2];
            int4 b = ((const int4*)(ei1 + NEDGE1))[u * 2 + 1];
            atomicAdd(&g_cnt1[a.x], 1); atomicAdd(&g_cnt1[a.y], 1);
            atomicAdd(&g_cnt1[a.z], 1); atomicAdd(&g_cnt1[a.w], 1);
            atomicAdd(&g_cnt1[b.x], 1); atomicAdd(&g_cnt1[b.y], 1);
            atomicAdd(&g_cnt1[b.z], 1); atomicAdd(&g_cnt1[b.w], 1);
        }
    }
    grid_sync(CSR_BLOCKS);

    // ---- phase 2: scan (blocks 0 and 1; cnt self-zeroed) ----
    if (blockIdx.x == 0)
        scan_phase(g_cnt0, g_rowptr0, g_cursor0, N_DST0, wsum, &carry_s);
    else if (blockIdx.x == 1)
        scan_phase(g_cnt1, g_rowptr1, g_cursor1, N_DST1, wsum, &carry_s);
    grid_sync(CSR_BLOCKS);

    // ---- phase 3: fill ----
    for (int t = t0; t < QT; t += gthreads) {
        if (t < Q0) {
            int4 sa = ((const int4*)ei0)[t * 2];
            int4 sb = ((const int4*)ei0)[t * 2 + 1];
            int4 da = ((const int4*)(ei0 + NEDGE0))[t * 2];
            int4 db = ((const int4*)(ei0 + NEDGE0))[t * 2 + 1];
            g_col0[atomicAdd(&g_cursor0[da.x], 1)] = sa.x;
            g_col0[atomicAdd(&g_cursor0[da.y], 1)] = sa.y;
            g_col0[atomicAdd(&g_cursor0[da.z], 1)] = sa.z;
            g_col0[atomicAdd(&g_cursor0[da.w], 1)] = sa.w;
            g_col0[atomicAdd(&g_cursor0[db.x], 1)] = sb.x;
            g_col0[atomicAdd(&g_cursor0[db.y], 1)] = sb.y;
            g_col0[atomicAdd(&g_cursor0[db.z], 1)] = sb.z;
            g_col0[atomicAdd(&g_cursor0[db.w], 1)] = sb.w;
        } else {
            int u = t - Q0;
            int4 sa = ((const int4*)ei1)[u * 2];
            int4 sb = ((const int4*)ei1)[u * 2 + 1];
            int4 da = ((const int4*)(ei1 + NEDGE1))[u * 2];
            int4 db = ((const int4*)(ei1 + NEDGE1))[u * 2 + 1];
            g_col1[atomicAdd(&g_cursor1[da.x], 1)] = sa.x;
            g_col1[atomicAdd(&g_cursor1[da.y], 1)] = sa.y;
            g_col1[atomicAdd(&g_cursor1[da.z], 1)] = sa.z;
            g_col1[atomicAdd(&g_cursor1[da.w], 1)] = sa.w;
            g_col1[atomicAdd(&g_cursor1[db.x], 1)] = sb.x;
            g_col1[atomicAdd(&g_cursor1[db.y], 1)] = sb.y;
            g_col1[atomicAdd(&g_cursor1[db.z], 1)] = sb.z;
            g_col1[atomicAdd(&g_cursor1[db.w], 1)] = sb.w;
        }
    }
}

// ---------------- dst-major aggregation (R12 proven versions) -----------------
__global__ void agg0_kernel(const float* __restrict__ x) {
    int w = (blockIdx.x * blockDim.x + threadIdx.x) >> 5;
    int lane = threadIdx.x & 31;
    if (w >= N_DST0) return;
    int beg = g_rowptr0[w], end = g_rowptr0[w + 1];
    float4 a0 = make_float4(0.f, 0.f, 0.f, 0.f);
    float4 a1 = a0, a2 = a0, a3 = a0;
    int e = beg;
    for (; e + 4 <= end; e += 4) {
        int s0 = g_col0[e], s1 = g_col0[e + 1], s2 = g_col0[e + 2], s3 = g_col0[e + 3];
        float4 v0 = ((const float4*)(x + (size_t)s0 * D_IN))[lane];
        float4 v1 = ((const float4*)(x + (size_t)s1 * D_IN))[lane];
        float4 v2 = ((const float4*)(x + (size_t)s2 * D_IN))[lane];
        float4 v3 = ((const float4*)(x + (size_t)s3 * D_IN))[lane];
        a0.x += v0.x; a0.y += v0.y; a0.z += v0.z; a0.w += v0.w;
        a1.x += v1.x; a1.y += v1.y; a1.z += v1.z; a1.w += v1.w;
        a2.x += v2.x; a2.y += v2.y; a2.z += v2.z; a2.w += v2.w;
        a3.x += v3.x; a3.y += v3.y; a3.z += v3.z; a3.w += v3.w;
    }
    for (; e < end; e++) {
        float4 v = ((const float4*)(x + (size_t)g_col0[e] * D_IN))[lane];
        a0.x += v.x; a0.y += v.y; a0.z += v.z; a0.w += v.w;
    }
    a0.x += a1.x + a2.x + a3.x;
    a0.y += a1.y + a2.y + a3.y;
    a0.z += a1.z + a2.z + a3.z;
    a0.w += a1.w + a2.w + a3.w;
    float s = 1.f / fmaxf((float)(end - beg), 1.f);
    a0.x *= s; a0.y *= s; a0.z *= s; a0.w *= s;
    ((float4*)(g_mean0 + (size_t)w * D_IN))[lane] = a0;
}

__global__ void agg1_kernel() {
    int w = (blockIdx.x * blockDim.x + threadIdx.x) >> 5;
    int lane = threadIdx.x & 31;
    if (w >= N_DST1) return;
    int beg = g_rowptr1[w], end = g_rowptr1[w + 1];
    float4 a0 = make_float4(0.f, 0.f, 0.f, 0.f);
    float4 a1 = a0, b0 = a0, b1 = a0;
    int e = beg;
    for (; e + 2 <= end; e += 2) {
        const float4* h0 = (const float4*)(g_h + (size_t)g_col1[e] * D_H);
        const float4* h1 = (const float4*)(g_h + (size_t)g_col1[e + 1] * D_H);
        float4 u0 = h0[lane], u1 = h0[lane + 32];
        float4 w0 = h1[lane], w1 = h1[lane + 32];
        a0.x += u0.x; a0.y += u0.y; a0.z += u0.z; a0.w += u0.w;
        a1.x += u1.x; a1.y += u1.y; a1.z += u1.z; a1.w += u1.w;
        b0.x += w0.x; b0.y += w0.y; b0.z += w0.z; b0.w += w0.w;
        b1.x += w1.x; b1.y += w1.y; b1.z += w1.z; b1.w += w1.w;
    }
    if (e < end) {
        const float4* h0 = (const float4*)(g_h + (size_t)g_col1[e] * D_H);
        float4 u0 = h0[lane], u1 = h0[lane + 32];
        a0.x += u0.x; a0.y += u0.y; a0.z += u0.z; a0.w += u0.w;
        a1.x += u1.x; a1.y += u1.y; a1.z += u1.z; a1.w += u1.w;
    }
    a0.x += b0.x; a0.y += b0.y; a0.z += b0.z; a0.w += b0.w;
    a1.x += b1.x; a1.y += b1.y; a1.z += b1.z; a1.w += b1.w;
    float s = 1.f / fmaxf((float)(end - beg), 1.f);
    a0.x *= s; a0.y *= s; a0.z *= s; a0.w *= s;
    a1.x *= s; a1.y *= s; a1.z *= s; a1.w *= s;
    float4* op = (float4*)(g_mean1 + (size_t)w * D_H);
    op[lane] = a0;
    op[lane + 32] = a1;
}

// ---------------- TF32 tensor-core dual-A GEMM --------------------------------
#define BM 128
#define BN 128
#define BK 16
#define AS_STRIDE 20
#define BS_STRIDE 136

__device__ __forceinline__ uint32_t f2tf32(float f) {
    uint32_t u;
    asm("cvt.rna.tf32.f32 %0, %1;" : "=r"(u) : "f"(f));
    return u;
}

__global__ void __launch_bounds__(256, 2)
gemm_dual_tf32_kernel(const float* __restrict__ A1,
                      const float* __restrict__ A2,
                      const float* __restrict__ W1, const float* __restrict__ W2,
                      const float* __restrict__ bias,
                      float* __restrict__ out, int M, int K, int do_relu) {
    __shared__ uint32_t As[BM * AS_STRIDE];
    __shared__ uint32_t Bs[BK * BS_STRIDE];

    const int tid  = threadIdx.x;
    const int lane = tid & 31;
    const int wrp  = tid >> 5;
    const int m_warp = (wrp & 1) * 64;
    const int n_warp = (wrp >> 1) * 32;
    const int bm = blockIdx.y * BM;
    const int bn = blockIdx.x * BN;

    const int a_r  = tid >> 2;
    const int a_kc = (tid & 3) * 4;
    const int b_kr = tid >> 5;
    const int b_c  = (tid & 31) * 4;

    float acc[4][4][4];
#pragma unroll
    for (int i = 0; i < 4; i++)
#pragma unroll
        for (int j = 0; j < 4; j++)
#pragma unroll
            for (int r = 0; r < 4; r++) acc[i][j][r] = 0.f;

    const int fr = lane >> 2;
    const int fc = lane & 3;

    for (int pass = 0; pass < 2; pass++) {
        const float* __restrict__ A = pass ? A2 : A1;
        const float* __restrict__ W = pass ? W2 : W1;
        const int gr0 = bm + a_r;
        const int gr1 = gr0 + 64;

        for (int k0 = 0; k0 < K; k0 += BK) {
            float4 av0 = make_float4(0.f, 0.f, 0.f, 0.f);
            float4 av1 = av0;
            if (gr0 < M) av0 = *(const float4*)&A[(size_t)gr0 * K + k0 + a_kc];
            if (gr1 < M) av1 = *(const float4*)&A[(size_t)gr1 * K + k0 + a_kc];
            float4 bv0 = *(const float4*)&W[(size_t)(k0 + b_kr) * D_H + bn + b_c];
            float4 bv1 = *(const float4*)&W[(size_t)(k0 + b_kr + 8) * D_H + bn + b_c];
            __syncthreads();
            {
                uint32_t* p0 = &As[a_r * AS_STRIDE + a_kc];
                p0[0] = f2tf32(av0.x); p0[1] = f2tf32(av0.y);
                p0[2] = f2tf32(av0.z); p0[3] = f2tf32(av0.w);
                uint32_t* p1 = &As[(a_r + 64) * AS_STRIDE + a_kc];
                p1[0] = f2tf32(av1.x); p1[1] = f2tf32(av1.y);
                p1[2] = f2tf32(av1.z); p1[3] = f2tf32(av1.w);
                uint32_t* q0 = &Bs[b_kr * BS_STRIDE + b_c];
                q0[0] = f2tf32(bv0.x); q0[1] = f2tf32(bv0.y);
                q0[2] = f2tf32(bv0.z); q0[3] = f2tf32(bv0.w);
                uint32_t* q1 = &Bs[(b_kr + 8) * BS_STRIDE + b_c];
                q1[0] = f2tf32(bv1.x); q1[1] = f2tf32(bv1.y);
                q1[2] = f2tf32(bv1.z); q1[3] = f2tf32(bv1.w);
            }
            __syncthreads();

#pragma unroll
            for (int ks = 0; ks < BK; ks += 8) {
                uint32_t af[4][4];
#pragma unroll
                for (int mt = 0; mt < 4; mt++) {
                    int rb = m_warp + mt * 16 + fr;
                    af[mt][0] = As[rb * AS_STRIDE + ks + fc];
                    af[mt][1] = As[(rb + 8) * AS_STRIDE + ks + fc];
                    af[mt][2] = As[rb * AS_STRIDE + ks + fc + 4];
                    af[mt][3] = As[(rb + 8) * AS_STRIDE + ks + fc + 4];
                }
                uint32_t bf[4][2];
#pragma unroll
                for (int nt = 0; nt < 4; nt++) {
                    int nb = n_warp + nt * 8 + fr;
                    bf[nt][0] = Bs[(ks + fc) * BS_STRIDE + nb];
                    bf[nt][1] = Bs[(ks + fc + 4) * BS_STRIDE + nb];
                }
#pragma unroll
                for (int mt = 0; mt < 4; mt++)
#pragma unroll
                    for (int nt = 0; nt < 4; nt++) {
                        asm volatile(
                            "mma.sync.aligned.m16n8k8.row.col.f32.tf32.tf32.f32 "
                            "{%0,%1,%2,%3}, {%4,%5,%6,%7}, {%8,%9}, {%0,%1,%2,%3};"
                            : "+f"(acc[mt][nt][0]), "+f"(acc[mt][nt][1]),
                              "+f"(acc[mt][nt][2]), "+f"(acc[mt][nt][3])
                            : "r"(af[mt][0]), "r"(af[mt][1]),
                              "r"(af[mt][2]), "r"(af[mt][3]),
                              "r"(bf[nt][0]), "r"(bf[nt][1]));
                    }
            }
        }
    }

#pragma unroll
    for (int mt = 0; mt < 4; mt++) {
#pragma unroll
        for (int nt = 0; nt < 4; nt++) {
            int col = bn + n_warp + nt * 8 + fc * 2;
            float b0 = bias[col], b1 = bias[col + 1];
            int r0 = bm + m_warp + mt * 16 + fr;
            int r1 = r0 + 8;
            float v0 = acc[mt][nt][0] + b0, v1 = acc[mt][nt][1] + b1;
            float v2 = acc[mt][nt][2] + b0, v3 = acc[mt][nt][3] + b1;
            if (do_relu) {
                v0 = fmaxf(v0, 0.f); v1 = fmaxf(v1, 0.f);
                v2 = fmaxf(v2, 0.f); v3 = fmaxf(v3, 0.f);
            }
            if (r0 < M) *(float2*)&out[(size_t)r0 * D_H + col] = make_float2(v0, v1);
            if (r1 < M) *(float2*)&out[(size_t)r1 * D_H + col] = make_float2(v2, v3);
        }
    }
}

// ---------------- epilogue: copy raw out + log_softmax ------------------------
__global__ void emit_kernel(const float* __restrict__ in,
                            float* __restrict__ out_raw,
                            float* __restrict__ out_ls) {
    int row = blockIdx.x;
    int t = threadIdx.x;
    float v = in[row * D_H + t];
    __shared__ float red[D_H];
    red[t] = v;
    __syncthreads();
#pragma unroll
    for (int s = 128; s > 0; s >>= 1) {
        if (t < s) red[t] = fmaxf(red[t], red[t + s]);
        __syncthreads();
    }
    float m = red[0];
    __syncthreads();
    float e = expf(v - m);
    red[t] = e;
    __syncthreads();
#pragma unroll
    for (int s = 128; s > 0; s >>= 1) {
        if (t < s) red[t] += red[t + s];
        __syncthreads();
    }
    float ls = v - m - logf(red[0]);
    if (out_raw) out_raw[row * D_H + t] = v;
    out_ls[row * D_H + t] = ls;
}

// ---------------- launch ------------------------------------------------------
extern "C" void kernel_launch(void* const* d_in, const int* in_sizes, int n_in,
                              void* d_out, int out_size) {
    const float* x     = (const float*)d_in[0];
    const int* ei0     = (const int*)d_in[1];
    const int* ei1     = (const int*)d_in[2];
    const float* W_l0  = (const float*)d_in[3];
    const float* b_l0  = (const float*)d_in[4];
    const float* W_r0  = (const float*)d_in[5];
    const float* W_l1  = (const float*)d_in[6];
    const float* b_l1  = (const float*)d_in[7];
    const float* W_r1  = (const float*)d_in[8];
    float* out         = (float*)d_out;

    float *p_mean0, *p_h, *p_mean1, *p_out;
    cudaGetSymbolAddress((void**)&p_mean0, g_mean0);
    cudaGetSymbolAddress((void**)&p_h,     g_h);
    cudaGetSymbolAddress((void**)&p_mean1, g_mean1);
    cudaGetSymbolAddress((void**)&p_out,   g_out);

    // fused CSR build (count -> scan -> fill, persistent grid + barriers)
    csr_build_kernel<<<CSR_BLOCKS, 256>>>(ei0, ei1);

    // layer 0: h = relu(mean0 @ W_l0 + b_l0 + x[:20000] @ W_r0)
    agg0_kernel<<<(N_DST0 * 32 + 255) / 256, 256>>>(x);
    gemm_dual_tf32_kernel<<<dim3(D_H / BN, (N_DST0 + BM - 1) / BM), 256>>>(
        p_mean0, x, W_l0, W_r0, b_l0, p_h, N_DST0, D_IN, 1);

    // layer 1: out = mean1 @ W_l1 + b_l1 + h[:4000] @ W_r1
    agg1_kernel<<<(N_DST1 * 32 + 255) / 256, 256>>>();
    gemm_dual_tf32_kernel<<<dim3(D_H / BN, (N_DST1 + BM - 1) / BM), 256>>>(
        p_mean1, p_h, W_l1, W_r1, b_l1, p_out, N_DST1, D_H, 0);

    const int NM = N_DST1 * D_H;
    float* out_raw = (out_size >= 2 * NM) ? out : nullptr;
    float* out_ls  = (out_size >= 2 * NM) ? out + NM : out;
    emit_kernel<<<N_DST1, D_H>>>(p_out, out_raw, out_ls);
}

// round 15
// speedup vs baseline: 1.0469x; 1.0469x over previous
#include <cuda_runtime.h>
#include <cstdint>

// ---------------- problem constants (fixed by reference setup) ----------------
#define N_SRC0 100000
#define N_DST0 20000
#define N_DST1 4000
#define NEDGE0 500000
#define NEDGE1 100000
#define D_IN 128
#define D_H 256

// ---------------- scratch (device globals; no allocation allowed) -------------
__device__ float g_mean0[N_DST0 * D_IN];
__device__ float g_h[N_DST0 * D_H];
__device__ float g_mean1[N_DST1 * D_H];

__device__ int g_cnt0[N_DST0];      // zero at load; re-zeroed by scan each run
__device__ int g_rowptr0[N_DST0 + 1];
__device__ int g_cursor0[N_DST0];
__device__ int g_col0[NEDGE0];
__device__ int g_cnt1[N_DST1];
__device__ int g_rowptr1[N_DST1 + 1];
__device__ int g_cursor1[N_DST1];
__device__ int g_col1[NEDGE1];

// ---------------- CSR: fused count, 8 edges/thread ----------------------------
__global__ void count2_kernel(const int* __restrict__ ei0,
                              const int* __restrict__ ei1) {
    const int Q0 = NEDGE0 / 8, Q1 = NEDGE1 / 8;
    int t = blockIdx.x * blockDim.x + threadIdx.x;
    if (t < Q0) {
        int4 a = ((const int4*)(ei0 + NEDGE0))[t * 2];
        int4 b = ((const int4*)(ei0 + NEDGE0))[t * 2 + 1];
        atomicAdd(&g_cnt0[a.x], 1); atomicAdd(&g_cnt0[a.y], 1);
        atomicAdd(&g_cnt0[a.z], 1); atomicAdd(&g_cnt0[a.w], 1);
        atomicAdd(&g_cnt0[b.x], 1); atomicAdd(&g_cnt0[b.y], 1);
        atomicAdd(&g_cnt0[b.z], 1); atomicAdd(&g_cnt0[b.w], 1);
    } else if (t < Q0 + Q1) {
        int u = t - Q0;
        int4 a = ((const int4*)(ei1 + NEDGE1))[u * 2];
        int4 b = ((const int4*)(ei1 + NEDGE1))[u * 2 + 1];
        atomicAdd(&g_cnt1[a.x], 1); atomicAdd(&g_cnt1[a.y], 1);
        atomicAdd(&g_cnt1[a.z], 1); atomicAdd(&g_cnt1[a.w], 1);
        atomicAdd(&g_cnt1[b.x], 1); atomicAdd(&g_cnt1[b.y], 1);
        atomicAdd(&g_cnt1[b.z], 1); atomicAdd(&g_cnt1[b.w], 1);
    }
}

// ---------------- scan: 8 elem/thread, 2 blocks, self-zeroing cnt -------------
__global__ void __launch_bounds__(1024, 1)
scan2_kernel() {
    const int layer = blockIdx.x;
    const int n     = layer ? N_DST1 : N_DST0;
    int* __restrict__ cnt    = layer ? g_cnt1    : g_cnt0;
    int* __restrict__ rowptr = layer ? g_rowptr1 : g_rowptr0;
    int* __restrict__ cursor = layer ? g_cursor1 : g_cursor0;

    __shared__ int wsum[32];
    __shared__ int carry_s;
    const int tid  = threadIdx.x;
    const int lane = tid & 31;
    const int wid  = tid >> 5;
    if (tid == 0) carry_s = 0;
    __syncthreads();

    const int4 z4 = make_int4(0, 0, 0, 0);
    for (int base = 0; base < n; base += 8192) {
        int i0 = base + tid * 8;
        int v[8];
        if (i0 + 8 <= n) {
            int4 a = *(const int4*)&cnt[i0];
            int4 b = *(const int4*)&cnt[i0 + 4];
            v[0] = a.x; v[1] = a.y; v[2] = a.z; v[3] = a.w;
            v[4] = b.x; v[5] = b.y; v[6] = b.z; v[7] = b.w;
            *(int4*)&cnt[i0] = z4;          // restore zero for next replay
            *(int4*)&cnt[i0 + 4] = z4;
        } else {
#pragma unroll
            for (int j = 0; j < 8; j++) {
                int ok = (i0 + j < n);
                v[j] = ok ? cnt[i0 + j] : 0;
                if (ok) cnt[i0 + j] = 0;
            }
        }
        int incl[8];
        int s = 0;
#pragma unroll
        for (int j = 0; j < 8; j++) { s += v[j]; incl[j] = s; }
        const int tot = s;
        int ws = tot;
#pragma unroll
        for (int off = 1; off < 32; off <<= 1) {
            int t = __shfl_up_sync(0xffffffffu, ws, off);
            if (lane >= off) ws += t;
        }
        if (lane == 31) wsum[wid] = ws;
        __syncthreads();
        if (wid == 0) {
            int w2 = wsum[lane];
#pragma unroll
            for (int off = 1; off < 32; off <<= 1) {
                int t = __shfl_up_sync(0xffffffffu, w2, off);
                if (lane >= off) w2 += t;
            }
            wsum[lane] = w2;
        }
        __syncthreads();
        int off0 = carry_s + ((wid > 0) ? wsum[wid - 1] : 0) + (ws - tot);
        if (i0 + 8 <= n) {
            int4 r0, r1;
            r0.x = off0 + incl[0] - v[0]; r0.y = off0 + incl[1] - v[1];
            r0.z = off0 + incl[2] - v[2]; r0.w = off0 + incl[3] - v[3];
            r1.x = off0 + incl[4] - v[4]; r1.y = off0 + incl[5] - v[5];
            r1.z = off0 + incl[6] - v[6]; r1.w = off0 + incl[7] - v[7];
            *(int4*)&rowptr[i0] = r0; *(int4*)&rowptr[i0 + 4] = r1;
            *(int4*)&cursor[i0] = r0; *(int4*)&cursor[i0 + 4] = r1;
        } else {
#pragma unroll
            for (int j = 0; j < 8; j++)
                if (i0 + j < n) {
                    int e = off0 + incl[j] - v[j];
                    rowptr[i0 + j] = e; cursor[i0 + j] = e;
                }
        }
        __syncthreads();
        if (tid == 0) carry_s += wsum[31];
        __syncthreads();
    }
    if (tid == 0) rowptr[n] = carry_s;
}

// ---------------- CSR: fused fill, 8 edges/thread -----------------------------
__global__ void fill2_kernel(const int* __restrict__ ei0,
                             const int* __restrict__ ei1) {
    const int Q0 = NEDGE0 / 8, Q1 = NEDGE1 / 8;
    int t = blockIdx.x * blockDim.x + threadIdx.x;
    if (t < Q0) {
        int4 sa = ((const int4*)ei0)[t * 2];
        int4 sb = ((const int4*)ei0)[t * 2 + 1];
        int4 da = ((const int4*)(ei0 + NEDGE0))[t * 2];
        int4 db = ((const int4*)(ei0 + NEDGE0))[t * 2 + 1];
        g_col0[atomicAdd(&g_cursor0[da.x], 1)] = sa.x;
        g_col0[atomicAdd(&g_cursor0[da.y], 1)] = sa.y;
        g_col0[atomicAdd(&g_cursor0[da.z], 1)] = sa.z;
        g_col0[atomicAdd(&g_cursor0[da.w], 1)] = sa.w;
        g_col0[atomicAdd(&g_cursor0[db.x], 1)] = sb.x;
        g_col0[atomicAdd(&g_cursor0[db.y], 1)] = sb.y;
        g_col0[atomicAdd(&g_cursor0[db.z], 1)] = sb.z;
        g_col0[atomicAdd(&g_cursor0[db.w], 1)] = sb.w;
    } else if (t < Q0 + Q1) {
        int u = t - Q0;
        int4 sa = ((const int4*)ei1)[u * 2];
        int4 sb = ((const int4*)ei1)[u * 2 + 1];
        int4 da = ((const int4*)(ei1 + NEDGE1))[u * 2];
        int4 db = ((const int4*)(ei1 + NEDGE1))[u * 2 + 1];
        g_col1[atomicAdd(&g_cursor1[da.x], 1)] = sa.x;
        g_col1[atomicAdd(&g_cursor1[da.y], 1)] = sa.y;
        g_col1[atomicAdd(&g_cursor1[da.z], 1)] = sa.z;
        g_col1[atomicAdd(&g_cursor1[da.w], 1)] = sa.w;
        g_col1[atomicAdd(&g_cursor1[db.x], 1)] = sb.x;
        g_col1[atomicAdd(&g_cursor1[db.y], 1)] = sb.y;
        g_col1[atomicAdd(&g_cursor1[db.z], 1)] = sb.z;
        g_col1[atomicAdd(&g_cursor1[db.w], 1)] = sb.w;
    }
}

// ---------------- dst-major aggregation (mean), no float atomics --------------
// layer0 (R12 proven): warp per dst, unroll 4.
__global__ void agg0_kernel(const float* __restrict__ x) {
    int w = (blockIdx.x * blockDim.x + threadIdx.x) >> 5;
    int lane = threadIdx.x & 31;
    if (w >= N_DST0) return;
    int beg = g_rowptr0[w], end = g_rowptr0[w + 1];
    float4 a0 = make_float4(0.f, 0.f, 0.f, 0.f);
    float4 a1 = a0, a2 = a0, a3 = a0;
    int e = beg;
    for (; e + 4 <= end; e += 4) {
        int s0 = g_col0[e], s1 = g_col0[e + 1], s2 = g_col0[e + 2], s3 = g_col0[e + 3];
        float4 v0 = ((const float4*)(x + (size_t)s0 * D_IN))[lane];
        float4 v1 = ((const float4*)(x + (size_t)s1 * D_IN))[lane];
        float4 v2 = ((const float4*)(x + (size_t)s2 * D_IN))[lane];
        float4 v3 = ((const float4*)(x + (size_t)s3 * D_IN))[lane];
        a0.x += v0.x; a0.y += v0.y; a0.z += v0.z; a0.w += v0.w;
        a1.x += v1.x; a1.y += v1.y; a1.z += v1.z; a1.w += v1.w;
        a2.x += v2.x; a2.y += v2.y; a2.z += v2.z; a2.w += v2.w;
        a3.x += v3.x; a3.y += v3.y; a3.z += v3.z; a3.w += v3.w;
    }
    for (; e < end; e++) {
        float4 v = ((const float4*)(x + (size_t)g_col0[e] * D_IN))[lane];
        a0.x += v.x; a0.y += v.y; a0.z += v.z; a0.w += v.w;
    }
    a0.x += a1.x + a2.x + a3.x;
    a0.y += a1.y + a2.y + a3.y;
    a0.z += a1.z + a2.z + a3.z;
    a0.w += a1.w + a2.w + a3.w;
    float s = 1.f / fmaxf((float)(end - beg), 1.f);
    a0.x *= s; a0.y *= s; a0.z *= s; a0.w *= s;
    ((float4*)(g_mean0 + (size_t)w * D_IN))[lane] = a0;
}

// layer1: TWO warps per dst (each owns half the 256-dim feature), unroll 4.
__global__ void agg1_kernel() {
    int gw = (blockIdx.x * blockDim.x + threadIdx.x) >> 5;
    int lane = threadIdx.x & 31;
    int w = gw >> 1;            // dst id
    int half = gw & 1;          // feature half: float4 index lane + half*32
    if (w >= N_DST1) return;
    int beg = g_rowptr1[w], end = g_rowptr1[w + 1];
    const int fo = lane + half * 32;
    float4 a0 = make_float4(0.f, 0.f, 0.f, 0.f);
    float4 a1 = a0, a2 = a0, a3 = a0;
    int e = beg;
    for (; e + 4 <= end; e += 4) {
        int s0 = g_col1[e], s1 = g_col1[e + 1], s2 = g_col1[e + 2], s3 = g_col1[e + 3];
        float4 v0 = ((const float4*)(g_h + (size_t)s0 * D_H))[fo];
        float4 v1 = ((const float4*)(g_h + (size_t)s1 * D_H))[fo];
        float4 v2 = ((const float4*)(g_h + (size_t)s2 * D_H))[fo];
        float4 v3 = ((const float4*)(g_h + (size_t)s3 * D_H))[fo];
        a0.x += v0.x; a0.y += v0.y; a0.z += v0.z; a0.w += v0.w;
        a1.x += v1.x; a1.y += v1.y; a1.z += v1.z; a1.w += v1.w;
        a2.x += v2.x; a2.y += v2.y; a2.z += v2.z; a2.w += v2.w;
        a3.x += v3.x; a3.y += v3.y; a3.z += v3.z; a3.w += v3.w;
    }
    for (; e < end; e++) {
        float4 v = ((const float4*)(g_h + (size_t)g_col1[e] * D_H))[fo];
        a0.x += v.x; a0.y += v.y; a0.z += v.z; a0.w += v.w;
    }
    a0.x += a1.x + a2.x + a3.x;
    a0.y += a1.y + a2.y + a3.y;
    a0.z += a1.z + a2.z + a3.z;
    a0.w += a1.w + a2.w + a3.w;
    float s = 1.f / fmaxf((float)(end - beg), 1.f);
    a0.x *= s; a0.y *= s; a0.z *= s; a0.w *= s;
    ((float4*)(g_mean1 + (size_t)w * D_H))[fo] = a0;
}

// ---------------- TF32 tensor-core dual-A GEMM --------------------------------
#define BM 128
#define BN 128
#define BK 16
#define AS_STRIDE 20
#define BS_STRIDE 136

__device__ __forceinline__ uint32_t f2tf32(float f) {
    uint32_t u;
    asm("cvt.rna.tf32.f32 %0, %1;" : "=r"(u) : "f"(f));
    return u;
}

__global__ void __launch_bounds__(256, 2)
gemm_dual_tf32_kernel(const float* __restrict__ A1,
                      const float* __restrict__ A2,
                      const float* __restrict__ W1, const float* __restrict__ W2,
                      const float* __restrict__ bias,
                      float* __restrict__ out, int M, int K, int do_relu) {
    __shared__ uint32_t As[BM * AS_STRIDE];
    __shared__ uint32_t Bs[BK * BS_STRIDE];

    const int tid  = threadIdx.x;
    const int lane = tid & 31;
    const int wrp  = tid >> 5;
    const int m_warp = (wrp & 1) * 64;
    const int n_warp = (wrp >> 1) * 32;
    const int bm = blockIdx.y * BM;
    const int bn = blockIdx.x * BN;

    const int a_r  = tid >> 2;
    const int a_kc = (tid & 3) * 4;
    const int b_kr = tid >> 5;
    const int b_c  = (tid & 31) * 4;

    float acc[4][4][4];
#pragma unroll
    for (int i = 0; i < 4; i++)
#pragma unroll
        for (int j = 0; j < 4; j++)
#pragma unroll
            for (int r = 0; r < 4; r++) acc[i][j][r] = 0.f;

    const int fr = lane >> 2;
    const int fc = lane & 3;

    for (int pass = 0; pass < 2; pass++) {
        const float* __restrict__ A = pass ? A2 : A1;
        const float* __restrict__ W = pass ? W2 : W1;
        const int gr0 = bm + a_r;
        const int gr1 = gr0 + 64;

        for (int k0 = 0; k0 < K; k0 += BK) {
            float4 av0 = make_float4(0.f, 0.f, 0.f, 0.f);
            float4 av1 = av0;
            if (gr0 < M) av0 = *(const float4*)&A[(size_t)gr0 * K + k0 + a_kc];
            if (gr1 < M) av1 = *(const float4*)&A[(size_t)gr1 * K + k0 + a_kc];
            float4 bv0 = *(const float4*)&W[(size_t)(k0 + b_kr) * D_H + bn + b_c];
            float4 bv1 = *(const float4*)&W[(size_t)(k0 + b_kr + 8) * D_H + bn + b_c];
            __syncthreads();
            {
                uint32_t* p0 = &As[a_r * AS_STRIDE + a_kc];
                p0[0] = f2tf32(av0.x); p0[1] = f2tf32(av0.y);
                p0[2] = f2tf32(av0.z); p0[3] = f2tf32(av0.w);
                uint32_t* p1 = &As[(a_r + 64) * AS_STRIDE + a_kc];
                p1[0] = f2tf32(av1.x); p1[1] = f2tf32(av1.y);
                p1[2] = f2tf32(av1.z); p1[3] = f2tf32(av1.w);
                uint32_t* q0 = &Bs[b_kr * BS_STRIDE + b_c];
                q0[0] = f2tf32(bv0.x); q0[1] = f2tf32(bv0.y);
                q0[2] = f2tf32(bv0.z); q0[3] = f2tf32(bv0.w);
                uint32_t* q1 = &Bs[(b_kr + 8) * BS_STRIDE + b_c];
                q1[0] = f2tf32(bv1.x); q1[1] = f2tf32(bv1.y);
                q1[2] = f2tf32(bv1.z); q1[3] = f2tf32(bv1.w);
            }
            __syncthreads();

#pragma unroll
            for (int ks = 0; ks < BK; ks += 8) {
                uint32_t af[4][4];
#pragma unroll
                for (int mt = 0; mt < 4; mt++) {
                    int rb = m_warp + mt * 16 + fr;
                    af[mt][0] = As[rb * AS_STRIDE + ks + fc];
                    af[mt][1] = As[(rb + 8) * AS_STRIDE + ks + fc];
                    af[mt][2] = As[rb * AS_STRIDE + ks + fc + 4];
                    af[mt][3] = As[(rb + 8) * AS_STRIDE + ks + fc + 4];
                }
                uint32_t bf[4][2];
#pragma unroll
                for (int nt = 0; nt < 4; nt++) {
                    int nb = n_warp + nt * 8 + fr;
                    bf[nt][0] = Bs[(ks + fc) * BS_STRIDE + nb];
                    bf[nt][1] = Bs[(ks + fc + 4) * BS_STRIDE + nb];
                }
#pragma unroll
                for (int mt = 0; mt < 4; mt++)
#pragma unroll
                    for (int nt = 0; nt < 4; nt++) {
                        asm volatile(
                            "mma.sync.aligned.m16n8k8.row.col.f32.tf32.tf32.f32 "
                            "{%0,%1,%2,%3}, {%4,%5,%6,%7}, {%8,%9}, {%0,%1,%2,%3};"
                            : "+f"(acc[mt][nt][0]), "+f"(acc[mt][nt][1]),
                              "+f"(acc[mt][nt][2]), "+f"(acc[mt][nt][3])
                            : "r"(af[mt][0]), "r"(af[mt][1]),
                              "r"(af[mt][2]), "r"(af[mt][3]),
                              "r"(bf[nt][0]), "r"(bf[nt][1]));
                    }
            }
        }
    }

#pragma unroll
    for (int mt = 0; mt < 4; mt++) {
#pragma unroll
        for (int nt = 0; nt < 4; nt++) {
            int col = bn + n_warp + nt * 8 + fc * 2;
            float b0 = bias[col], b1 = bias[col + 1];
            int r0 = bm + m_warp + mt * 16 + fr;
            int r1 = r0 + 8;
            float v0 = acc[mt][nt][0] + b0, v1 = acc[mt][nt][1] + b1;
            float v2 = acc[mt][nt][2] + b0, v3 = acc[mt][nt][3] + b1;
            if (do_relu) {
                v0 = fmaxf(v0, 0.f); v1 = fmaxf(v1, 0.f);
                v2 = fmaxf(v2, 0.f); v3 = fmaxf(v3, 0.f);
            }
            if (r0 < M) *(float2*)&out[(size_t)r0 * D_H + col] = make_float2(v0, v1);
            if (r1 < M) *(float2*)&out[(size_t)r1 * D_H + col] = make_float2(v2, v3);
        }
    }
}

// ---------------- epilogue: log_softmax (reads raw logits already in d_out) ---
__global__ void emit_kernel(const float* __restrict__ in,
                            float* __restrict__ out_ls) {
    int row = blockIdx.x;
    int t = threadIdx.x;
    float v = in[row * D_H + t];
    __shared__ float red[D_H];
    red[t] = v;
    __syncthreads();
#pragma unroll
    for (int s = 128; s > 0; s >>= 1) {
        if (t < s) red[t] = fmaxf(red[t], red[t + s]);
        __syncthreads();
    }
    float m = red[0];
    __syncthreads();
    float e = expf(v - m);
    red[t] = e;
    __syncthreads();
#pragma unroll
    for (int s = 128; s > 0; s >>= 1) {
        if (t < s) red[t] += red[t + s];
        __syncthreads();
    }
    out_ls[row * D_H + t] = v - m - logf(red[0]);
}

// ---------------- launch ------------------------------------------------------
extern "C" void kernel_launch(void* const* d_in, const int* in_sizes, int n_in,
                              void* d_out, int out_size) {
    const float* x     = (const float*)d_in[0];
    const int* ei0     = (const int*)d_in[1];
    const int* ei1     = (const int*)d_in[2];
    const float* W_l0  = (const float*)d_in[3];
    const float* b_l0  = (const float*)d_in[4];
    const float* W_r0  = (const float*)d_in[5];
    const float* W_l1  = (const float*)d_in[6];
    const float* b_l1  = (const float*)d_in[7];
    const float* W_r1  = (const float*)d_in[8];
    float* out         = (float*)d_out;

    float *p_mean0, *p_h, *p_mean1;
    cudaGetSymbolAddress((void**)&p_mean0, g_mean0);
    cudaGetSymbolAddress((void**)&p_h,     g_h);
    cudaGetSymbolAddress((void**)&p_mean1, g_mean1);

    const int QTOT = NEDGE0 / 8 + NEDGE1 / 8;   // 75000 threads
    const int NM = N_DST1 * D_H;
    // raw logits land at out[0:NM]; log_softmax at out[NM:2NM] (if room)
    float* out_raw = out;
    float* out_ls  = (out_size >= 2 * NM) ? out + NM : out;

    // CSR build (both layers fused per stage, self-zeroing counts)
    count2_kernel<<<(QTOT + 255) / 256, 256>>>(ei0, ei1);
    scan2_kernel<<<2, 1024>>>();
    fill2_kernel<<<(QTOT + 255) / 256, 256>>>(ei0, ei1);

    // layer 0: h = relu(mean0 @ W_l0 + b_l0 + x[:20000] @ W_r0)
    agg0_kernel<<<(N_DST0 * 32 + 255) / 256, 256>>>(x);
    gemm_dual_tf32_kernel<<<dim3(D_H / BN, (N_DST0 + BM - 1) / BM), 256>>>(
        p_mean0, x, W_l0, W_r0, b_l0, p_h, N_DST0, D_IN, 1);

    // layer 1: logits = mean1 @ W_l1 + b_l1 + h[:4000] @ W_r1  -> directly to out
    agg1_kernel<<<(N_DST1 * 64 + 255) / 256, 256>>>();
    gemm_dual_tf32_kernel<<<dim3(D_H / BN, (N_DST1 + BM - 1) / BM), 256>>>(
        p_mean1, p_h, W_l1, W_r1, b_l1, out_raw, N_DST1, D_H, 0);

    emit_kernel<<<N_DST1, D_H>>>(out_raw, out_ls);
}